// round 4
// baseline (speedup 1.0000x reference)
#include <cuda_runtime.h>

#define NPERSEG 1024
#define STEP     256
#define SEQ    16384
#define NWIN      61
#define BATCH   1024
#define THREADS  256

#define CTILE   2048                 // samples per column block
#define CF4     (CTILE / 4)          // 512 float4 per column block
#define RTILE   8                    // rows per CTA
#define NCB     (SEQ / CTILE)        // 8 column blocks
#define NRB     (BATCH / RTILE)      // 128 row blocks

// Per-(row, col-block) partial sums (re, im). Each slot written exactly once.
__device__ float2 g_part[BATCH * NCB];

// One fused kernel: CTA (cb, rb) covers rows [rb*8, rb*8+8) x samples
// [cb*2048, cb*2048+2048). It builds its own weight chunk in smem from the
// freqs vector (warp-uniform window predicates), then streams 8 rows.
__global__ __launch_bounds__(THREADS) void welch_main_kernel(
    const float4* __restrict__ in,
    const float*  __restrict__ freqs)
{
    __shared__ float2 s_cs[NPERSEG];   // 8 KB: (cos, sin) of 2*pi*freqs[p]
    __shared__ float  s_wre[CTILE];    // 8 KB (reused as reduce scratch)
    __shared__ float  s_wim[CTILE];    // 8 KB (reused as reduce scratch)

    const int cb  = blockIdx.x;
    const int rb  = blockIdx.y;
    const int tid = threadIdx.x;
    const float TWO_PI = 6.283185307179586476925f;

    // --- Stage 1: sincos table for all 1024 freq bins (4 per thread) ---
    #pragma unroll
    for (int k = 0; k < 4; ++k) {
        int p = tid + k * STEP;
        float sn, cs;
        sincosf(TWO_PI * freqs[p], &sn, &cs);
        s_cs[p] = make_float2(cs, sn);
    }
    __syncthreads();

    // --- Stage 2: build this column block's 2048 weights ---
    // sample s = cb*2048 + j*256 + tid; window w = cb*8 + j - k, valid iff
    // 0 <= w < NWIN. Predicate depends only on (cb, j, k): uniform.
    const float inv = 1.0f / (float)NWIN;
    #pragma unroll
    for (int j = 0; j < 8; ++j) {
        const int wbase = cb * 8 + j;
        float wre = 0.f, wim = 0.f;
        #pragma unroll
        for (int k = 0; k < 4; ++k) {
            if (wbase - k >= 0 && wbase - k < NWIN) {
                float2 cs = s_cs[tid + k * STEP];
                wre += cs.x;
                wim -= cs.y;
            }
        }
        s_wre[j * THREADS + tid] = wre * inv;
        s_wim[j * THREADS + tid] = wim * inv;
    }
    __syncthreads();

    // --- Stage 3: stream 8 rows of this column block ---
    const int row0 = rb * RTILE;
    const float4* __restrict__ base =
        in + (size_t)row0 * (SEQ / 4) + cb * CF4;
    const float4* __restrict__ wre4 = (const float4*)s_wre;
    const float4* __restrict__ wim4 = (const float4*)s_wim;

    float accre[RTILE], accim[RTILE];
    #pragma unroll
    for (int r = 0; r < RTILE; ++r) { accre[r] = 0.f; accim[r] = 0.f; }

    #pragma unroll
    for (int g = 0; g < CF4 / THREADS; ++g) {
        const int l = g * THREADS + tid;
        const float4 cr = wre4[l];
        const float4 ci = wim4[l];

        float4 x[RTILE];
        #pragma unroll
        for (int r = 0; r < RTILE; ++r)
            x[r] = __ldcg(base + (size_t)r * (SEQ / 4) + l);

        #pragma unroll
        for (int r = 0; r < RTILE; ++r) {
            accre[r] = fmaf(x[r].x, cr.x, accre[r]);
            accre[r] = fmaf(x[r].y, cr.y, accre[r]);
            accre[r] = fmaf(x[r].z, cr.z, accre[r]);
            accre[r] = fmaf(x[r].w, cr.w, accre[r]);
            accim[r] = fmaf(x[r].x, ci.x, accim[r]);
            accim[r] = fmaf(x[r].y, ci.y, accim[r]);
            accim[r] = fmaf(x[r].z, ci.z, accim[r]);
            accim[r] = fmaf(x[r].w, ci.w, accim[r]);
        }
    }

    // --- Stage 4: block reduce per row (reuse s_wre/s_wim as scratch) ---
    __syncthreads();
    #pragma unroll
    for (int r = 0; r < RTILE; ++r) {
        s_wre[r * THREADS + tid] = accre[r];
        s_wim[r * THREADS + tid] = accim[r];
    }
    __syncthreads();

    const int w    = tid >> 5;     // warp w reduces row w (8 warps, 8 rows)
    const int lane = tid & 31;
    float vre = 0.f, vim = 0.f;
    #pragma unroll
    for (int k = 0; k < THREADS / 32; ++k) {
        vre += s_wre[w * THREADS + k * 32 + lane];
        vim += s_wim[w * THREADS + k * 32 + lane];
    }
    #pragma unroll
    for (int off = 16; off > 0; off >>= 1) {
        vre += __shfl_xor_sync(0xffffffffu, vre, off);
        vim += __shfl_xor_sync(0xffffffffu, vim, off);
    }
    if (lane == 0)
        g_part[(row0 + w) * NCB + cb] = make_float2(vre, vim);
}

__global__ void epilogue_kernel(const float* __restrict__ fc_w,
                                const float* __restrict__ fc_b,
                                float* __restrict__ out)
{
    int b = blockIdx.x * blockDim.x + threadIdx.x;
    if (b >= BATCH) return;
    float fr = 0.f, fi = 0.f;
    #pragma unroll
    for (int c = 0; c < NCB; ++c) {
        float2 p = g_part[b * NCB + c];
        fr += p.x;
        fi += p.y;
    }
    float psd = fr * fr + fi * fi;
    out[b] = fmaf(psd, fc_w[0], fc_b[0]);
}

extern "C" void kernel_launch(void* const* d_in, const int* in_sizes, int n_in,
                              void* d_out, int out_size) {
    const float* input = (const float*)d_in[0];   // (1024, 16384) f32
    const float* freqs = (const float*)d_in[1];   // (1024,) f32
    const float* fc_w  = (const float*)d_in[2];   // (1,1) f32
    const float* fc_b  = (const float*)d_in[3];   // (1,) f32
    float* out = (float*)d_out;                   // (1024, 1) f32

    welch_main_kernel<<<dim3(NCB, NRB), THREADS>>>((const float4*)input, freqs);
    epilogue_kernel<<<4, 256>>>(fc_w, fc_b, out);
}